// round 1
// baseline (speedup 1.0000x reference)
#include <cuda_runtime.h>
#include <math.h>

#define EPSF  1e-6f
#define TINYF 1e-15f

#define MAX_M 16384
#define MAX_D 2048

// Scratch (no allocations allowed): GEMM result t = x @ W^T, and per-row log0 coefs.
__device__ float g_t[(size_t)MAX_M * MAX_D];
__device__ float g_c[MAX_M];

// ---------------------------------------------------------------------------
// Kernel 1: per-row log0 coefficient  c[n] = asinh(||x_n||) / max(||x_n||, EPS)
// ---------------------------------------------------------------------------
__global__ void __launch_bounds__(256)
rowcoef_kernel(const float* __restrict__ x, float* __restrict__ c, int K)
{
    const int n = blockIdx.x;
    const float* row = x + (size_t)n * K;

    float s = 0.f;
    for (int k = threadIdx.x * 4; k < K; k += blockDim.x * 4) {
        float4 v = *(const float4*)(row + k);
        s += v.x * v.x + v.y * v.y + v.z * v.z + v.w * v.w;
    }

    // block reduction
    #pragma unroll
    for (int o = 16; o > 0; o >>= 1) s += __shfl_xor_sync(0xffffffffu, s, o);
    __shared__ float sh[8];
    const int warp = threadIdx.x >> 5;
    const int lane = threadIdx.x & 31;
    if (lane == 0) sh[warp] = s;
    __syncthreads();
    if (threadIdx.x == 0) {
        float tot = 0.f;
        #pragma unroll
        for (int w = 0; w < 8; w++) tot += sh[w];
        float nrm = sqrtf(tot);
        c[n] = asinhf(nrm) / fmaxf(nrm, EPSF);
    }
}

// ---------------------------------------------------------------------------
// Kernel 2: t = A @ B^T  (A: MxK row-major, B: NxK row-major, C: MxN row-major)
// Classic 128x128x16 tile, 256 threads, 8x8 per-thread microtile, fp32.
// ---------------------------------------------------------------------------
#define BM 128
#define BN 128
#define BK 16
#define TM 8
#define TN 8

__global__ void __launch_bounds__(256, 2)
gemm_nt_kernel(const float* __restrict__ A, const float* __restrict__ B,
               float* __restrict__ C, int M, int N, int K)
{
    __shared__ float As[BK][BM + 4];
    __shared__ float Bs[BK][BN + 4];

    const int bm  = blockIdx.y * BM;
    const int bn  = blockIdx.x * BN;
    const int tid = threadIdx.x;
    const int tr  = tid >> 4;          // 0..15 (row of thread grid)
    const int tc  = tid & 15;          // 0..15 (col of thread grid)

    const int lrow = tid >> 2;         // 0..63
    const int lcol = (tid & 3) << 2;   // 0,4,8,12

    const float* Ab = A + (size_t)bm * K;
    const float* Bb = B + (size_t)bn * K;

    float acc[TM][TN];
    #pragma unroll
    for (int i = 0; i < TM; i++)
        #pragma unroll
        for (int j = 0; j < TN; j++) acc[i][j] = 0.f;

    for (int k0 = 0; k0 < K; k0 += BK) {
        #pragma unroll
        for (int h = 0; h < 2; h++) {
            const int r = lrow + h * 64;
            float4 va = *(const float4*)(Ab + (size_t)r * K + k0 + lcol);
            As[lcol + 0][r] = va.x; As[lcol + 1][r] = va.y;
            As[lcol + 2][r] = va.z; As[lcol + 3][r] = va.w;
            float4 vb = *(const float4*)(Bb + (size_t)r * K + k0 + lcol);
            Bs[lcol + 0][r] = vb.x; Bs[lcol + 1][r] = vb.y;
            Bs[lcol + 2][r] = vb.z; Bs[lcol + 3][r] = vb.w;
        }
        __syncthreads();

        #pragma unroll
        for (int k = 0; k < BK; k++) {
            float af[TM], bf[TN];
            *(float4*)&af[0] = *(const float4*)&As[k][tr * TM];
            *(float4*)&af[4] = *(const float4*)&As[k][tr * TM + 4];
            *(float4*)&bf[0] = *(const float4*)&Bs[k][tc * TN];
            *(float4*)&bf[4] = *(const float4*)&Bs[k][tc * TN + 4];
            #pragma unroll
            for (int i = 0; i < TM; i++)
                #pragma unroll
                for (int j = 0; j < TN; j++)
                    acc[i][j] = fmaf(af[i], bf[j], acc[i][j]);
        }
        __syncthreads();
    }

    float* Cb = C + (size_t)(bm + tr * TM) * N + bn + tc * TN;
    #pragma unroll
    for (int i = 0; i < TM; i++) {
        *(float4*)(Cb + (size_t)i * N + 0) =
            make_float4(acc[i][0], acc[i][1], acc[i][2], acc[i][3]);
        *(float4*)(Cb + (size_t)i * N + 4) =
            make_float4(acc[i][4], acc[i][5], acc[i][6], acc[i][7]);
    }
}

// ---------------------------------------------------------------------------
// Kernel 3: fused epilogue. For each row n (with u = c_n * t_n):
//   proj_tan0 -> exp0 -> pt_0_to_y -> exp_map (gyro_add)
// All of it collapses to:  out[n,:] = gamma_n * t[n,:] + A_n * b[:]
// where gamma_n, A_n come from row scalars St2=sum t^2, Stb=sum t*b, Sb2=sum b^2.
// ---------------------------------------------------------------------------
__global__ void __launch_bounds__(512)
epilogue_kernel(const float* __restrict__ T, const float* __restrict__ bvec,
                const float* __restrict__ cvec, float* __restrict__ out, int D)
{
    const int n = blockIdx.x;
    const float* trow = T + (size_t)n * D;
    const int k = threadIdx.x * 4;   // D == 2048, 512 threads * 4 = 2048

    float4 tv = *(const float4*)(trow + k);
    float4 bv = *(const float4*)(bvec + k);

    float st2 = tv.x * tv.x + tv.y * tv.y + tv.z * tv.z + tv.w * tv.w;
    float stb = tv.x * bv.x + tv.y * bv.y + tv.z * bv.z + tv.w * bv.w;
    float sb2 = bv.x * bv.x + bv.y * bv.y + bv.z * bv.z + bv.w * bv.w;

    // joint block reduction of 3 sums
    #pragma unroll
    for (int o = 16; o > 0; o >>= 1) {
        st2 += __shfl_xor_sync(0xffffffffu, st2, o);
        stb += __shfl_xor_sync(0xffffffffu, stb, o);
        sb2 += __shfl_xor_sync(0xffffffffu, sb2, o);
    }
    __shared__ float sh[16][3];
    __shared__ float tot[3];
    const int warp = threadIdx.x >> 5;
    const int lane = threadIdx.x & 31;
    if (lane == 0) { sh[warp][0] = st2; sh[warp][1] = stb; sh[warp][2] = sb2; }
    __syncthreads();
    if (warp == 0) {
        float a = (lane < 16) ? sh[lane][0] : 0.f;
        float b2 = (lane < 16) ? sh[lane][1] : 0.f;
        float c2 = (lane < 16) ? sh[lane][2] : 0.f;
        #pragma unroll
        for (int o = 8; o > 0; o >>= 1) {
            a  += __shfl_xor_sync(0xffffffffu, a,  o);
            b2 += __shfl_xor_sync(0xffffffffu, b2, o);
            c2 += __shfl_xor_sync(0xffffffffu, c2, o);
        }
        if (lane == 0) { tot[0] = a; tot[1] = b2; tot[2] = c2; }
    }
    __syncthreads();

    const float St2 = tot[0];
    const float Stb = tot[1];
    const float Sb2 = tot[2];
    const float cn  = cvec[n];

    // ---- scalar chain (replicates reference fp32 math) ----
    // u = cn * t
    const float r      = cn * sqrtf(St2);                       // ||u||
    const float scale1 = fminf(20.0f / fmaxf(r, EPSF), 1.0f);   // proj_tan0
    const float rp     = scale1 * r;                            // ||u'||
    const float coef0  = sinhf(rp) / fmaxf(rp, EPSF);           // exp0 coef
    const float m      = coef0 * scale1 * cn;                   // y = m * t
    const float ry2    = m * m * St2;                           // ||y||^2
    const float dot    = m * Stb;                               // <y, b>

    const float b_y   = 1.0f / fmaxf(sqrtf(1.0f + ry2), TINYF); // beta(y)
    const float coefp = b_y / (1.0f + b_y);
    const float p     = coefp * dot;                            // bt = b + p*y

    const float v_norm2 = Sb2 + 2.0f * p * dot + p * p * ry2;   // ||bt||^2
    const float dxv     = dot + p * ry2;                        // <y, bt>
    const float g_pvv   = fmaxf(v_norm2 - dxv * dxv / (1.0f + ry2), TINYF);
    const float r_g     = sqrtf(g_pvv);

    const float coef2    = -(b_y * b_y * b_y) / ((1.0f + b_y) * (1.0f + b_y));
    const float lambda_x = (1.0f + b_y) / fmaxf(b_y, TINYF);
    const float z        = fminf(r_g, 20.0f);                   // clip (r_g >= 0)
    float sc;
    if (fabsf(z) < EPSF) sc = 1.0f + z * z / 6.0f;
    else                 sc = sinhf(z) / fmaxf(z, EPSF);
    const float L = lambda_x * sc;

    // w = L*(coefp*bt + coef2*dxv*y) = A*b + Bw*y
    const float A  = L * coefp;
    const float Bw = A * p + L * coef2 * dxv;

    const float w2 = A * A * Sb2 + 2.0f * A * Bw * dot + Bw * Bw * ry2; // ||w||^2
    const float xw = A * dot + Bw * ry2;                                // <y, w>
    const float b_w = 1.0f / fmaxf(sqrtf(1.0f + w2), TINYF);
    const float coef_g = coefp * xw + (1.0f - b_w) / b_w;

    // out = (1 + coef_g)*y + w = (1 + coef_g + Bw)*y + A*b ; y = m*t
    const float gamma = (1.0f + coef_g + Bw) * m;

    float4 ov;
    ov.x = gamma * tv.x + A * bv.x;
    ov.y = gamma * tv.y + A * bv.y;
    ov.z = gamma * tv.z + A * bv.z;
    ov.w = gamma * tv.w + A * bv.w;
    *(float4*)(out + (size_t)n * D + k) = ov;
}

// ---------------------------------------------------------------------------
extern "C" void kernel_launch(void* const* d_in, const int* in_sizes, int n_in,
                              void* d_out, int out_size)
{
    const float* x = (const float*)d_in[0];   // [M, K]
    const float* W = (const float*)d_in[1];   // [D, K]
    const float* b = (const float*)d_in[2];   // [D]
    float* out = (float*)d_out;

    const int D = in_sizes[2];              // 2048
    const int K = in_sizes[1] / D;          // 2048
    const int M = in_sizes[0] / K;          // 16384

    void* pt = nullptr; cudaGetSymbolAddress(&pt, g_t);
    void* pc = nullptr; cudaGetSymbolAddress(&pc, g_c);
    float* T    = (float*)pt;
    float* cvec = (float*)pc;

    rowcoef_kernel<<<M, 256>>>(x, cvec, K);
    dim3 grid(D / BN, M / BM);
    gemm_nt_kernel<<<grid, 256>>>(x, W, T, M, D, K);
    epilogue_kernel<<<M, 512>>>(T, b, cvec, out, D);
}

// round 3
// speedup vs baseline: 1.2654x; 1.2654x over previous
#include <cuda_runtime.h>
#include <cuda_bf16.h>
#include <math.h>
#include <stdint.h>

#define EPSF  1e-6f
#define TINYF 1e-15f

#define MAX_M 16384
#define MAX_K 2048
#define MAX_D 2048

// ---------------- scratch (static device allocations only) ----------------
__device__ float g_t[(size_t)MAX_M * MAX_D];          // GEMM result (fp32)
__device__ float g_c[MAX_M];                          // log0 row coefs
__device__ __nv_bfloat16 g_Ahi[(size_t)MAX_M * MAX_K];
__device__ __nv_bfloat16 g_Alo[(size_t)MAX_M * MAX_K];
__device__ __nv_bfloat16 g_Bhi[(size_t)MAX_D * MAX_K];
__device__ __nv_bfloat16 g_Blo[(size_t)MAX_D * MAX_K];

// ---------------- helpers ----------------
__device__ __forceinline__ uint32_t smem_u32(const void* p) {
    uint32_t a;
    asm("{ .reg .u64 t; cvta.to.shared.u64 t, %1; cvt.u32.u64 %0, t; }" : "=r"(a) : "l"(p));
    return a;
}
#define CP16(dst, src) \
    asm volatile("cp.async.cg.shared.global [%0], [%1], 16;" :: "r"(dst), "l"(src) : "memory")
#define CP_COMMIT() asm volatile("cp.async.commit_group;" ::: "memory")
#define CP_WAIT(n)  asm volatile("cp.async.wait_group %0;" :: "n"(n) : "memory")

__device__ __forceinline__ void mma16816(float* c, const uint32_t* a, const uint32_t* b) {
    asm volatile(
        "mma.sync.aligned.m16n8k16.row.col.f32.bf16.bf16.f32 "
        "{%0,%1,%2,%3}, {%4,%5,%6,%7}, {%8,%9}, {%0,%1,%2,%3};"
        : "+f"(c[0]), "+f"(c[1]), "+f"(c[2]), "+f"(c[3])
        : "r"(a[0]), "r"(a[1]), "r"(a[2]), "r"(a[3]), "r"(b[0]), "r"(b[1]));
}

// ---------------------------------------------------------------------------
// Kernel 1: split fp32 row -> (hi, lo) bf16; optionally also log0 coef c[n]
// ---------------------------------------------------------------------------
__global__ void __launch_bounds__(256)
convert_split_kernel(const float* __restrict__ src, __nv_bfloat16* __restrict__ hi,
                     __nv_bfloat16* __restrict__ lo, float* __restrict__ c,
                     int K, int compute_c)
{
    const int n = blockIdx.x;
    const float* row = src + (size_t)n * K;
    __nv_bfloat16* hrow = hi + (size_t)n * K;
    __nv_bfloat16* lrow = lo + (size_t)n * K;

    float s = 0.f;
    for (int k = threadIdx.x * 4; k < K; k += blockDim.x * 4) {
        float4 v = *(const float4*)(row + k);
        s += v.x * v.x + v.y * v.y + v.z * v.z + v.w * v.w;
        __nv_bfloat16 h0 = __float2bfloat16(v.x);
        __nv_bfloat16 h1 = __float2bfloat16(v.y);
        __nv_bfloat16 h2 = __float2bfloat16(v.z);
        __nv_bfloat16 h3 = __float2bfloat16(v.w);
        __nv_bfloat16 l0 = __float2bfloat16(v.x - __bfloat162float(h0));
        __nv_bfloat16 l1 = __float2bfloat16(v.y - __bfloat162float(h1));
        __nv_bfloat16 l2 = __float2bfloat16(v.z - __bfloat162float(h2));
        __nv_bfloat16 l3 = __float2bfloat16(v.w - __bfloat162float(h3));
        ushort4 hu = make_ushort4(*(unsigned short*)&h0, *(unsigned short*)&h1,
                                  *(unsigned short*)&h2, *(unsigned short*)&h3);
        ushort4 lu = make_ushort4(*(unsigned short*)&l0, *(unsigned short*)&l1,
                                  *(unsigned short*)&l2, *(unsigned short*)&l3);
        *(ushort4*)(hrow + k) = hu;
        *(ushort4*)(lrow + k) = lu;
    }
    if (!compute_c) return;

    #pragma unroll
    for (int o = 16; o > 0; o >>= 1) s += __shfl_xor_sync(0xffffffffu, s, o);
    __shared__ float sh[8];
    const int warp = threadIdx.x >> 5, lane = threadIdx.x & 31;
    if (lane == 0) sh[warp] = s;
    __syncthreads();
    if (threadIdx.x == 0) {
        float tot = 0.f;
        #pragma unroll
        for (int w = 0; w < 8; w++) tot += sh[w];
        float nrm = sqrtf(tot);
        c[n] = asinhf(nrm) / fmaxf(nrm, EPSF);
    }
}

// ---------------------------------------------------------------------------
// Kernel 2: t = x @ W^T via split-bf16 3-term sum on mma.sync.m16n8k16.
// BM=128, BN=128, BK=32, 3-stage cp.async pipeline, 256 threads, 2x4 warps,
// warp tile 64x32. Smem rows padded to 40 elems -> conflict-free LDS.32 frags.
// ---------------------------------------------------------------------------
#define BM 128
#define BN 128
#define BK 32
#define STAGES 3
#define ASTRIDE (BK + 8)                         // 40 elems = 80 B rows
#define A_STAGE_ELEMS (BM * ASTRIDE)             // 5120
#define B_STAGE_ELEMS (BN * ASTRIDE)             // 5120
#define STAGE_ELEMS (A_STAGE_ELEMS + B_STAGE_ELEMS)
#define SMEM_BYTES (STAGES * STAGE_ELEMS * 2)    // 61440

__global__ void __launch_bounds__(256, 2)
gemm_mma_kernel(const __nv_bfloat16* __restrict__ Ahi, const __nv_bfloat16* __restrict__ Alo,
                const __nv_bfloat16* __restrict__ Bhi, const __nv_bfloat16* __restrict__ Blo,
                float* __restrict__ C, int M, int N, int K)
{
    extern __shared__ __nv_bfloat16 sm[];

    const int tid  = threadIdx.x;
    const int warp = tid >> 5;
    const int lane = tid & 31;
    const int lr   = lane >> 2;     // 0..7
    const int lc   = lane & 3;      // 0..3
    const int wr   = (warp >> 2) * 64;   // warp row offset in tile (0 or 64)
    const int wc   = (warp & 3) * 32;    // warp col offset (0,32,64,96)

    const int bm = blockIdx.y * BM;
    const int bn = blockIdx.x * BN;

    const int KITER = K / BK;       // 64
    const int NIT   = 3 * KITER;    // 192

    float acc[4][4][4];
    #pragma unroll
    for (int i = 0; i < 4; i++)
        #pragma unroll
        for (int j = 0; j < 4; j++)
            #pragma unroll
            for (int q = 0; q < 4; q++) acc[i][j][q] = 0.f;

    // ---- stage loader ----
    auto load_stage = [&](int g, int s) {
        const int seg = g / KITER;
        const int kk  = (g - seg * KITER) * BK;
        const __nv_bfloat16* Ag = (seg == 1) ? Alo : Ahi;
        const __nv_bfloat16* Bg = (seg == 2) ? Blo : Bhi;
        __nv_bfloat16* As = sm + s * STAGE_ELEMS;
        __nv_bfloat16* Bs = As + A_STAGE_ELEMS;
        #pragma unroll
        for (int i = 0; i < 2; i++) {
            const int id  = tid + i * 256;      // 0..511
            const int row = id >> 2;            // 0..127
            const int cg  = id & 3;             // 16B chunk in row
            CP16(smem_u32(As + row * ASTRIDE + cg * 8),
                 Ag + (size_t)(bm + row) * K + kk + cg * 8);
            CP16(smem_u32(Bs + row * ASTRIDE + cg * 8),
                 Bg + (size_t)(bn + row) * K + kk + cg * 8);
        }
    };

    // prologue
    #pragma unroll
    for (int s = 0; s < STAGES - 1; s++) { load_stage(s, s); CP_COMMIT(); }

    for (int g = 0; g < NIT; ++g) {
        CP_WAIT(STAGES - 2);
        __syncthreads();

        const int gn = g + STAGES - 1;
        if (gn < NIT) load_stage(gn, gn % STAGES);
        CP_COMMIT();

        const __nv_bfloat16* As = sm + (g % STAGES) * STAGE_ELEMS;
        const __nv_bfloat16* Bs = As + A_STAGE_ELEMS;

        #pragma unroll
        for (int ks = 0; ks < BK; ks += 16) {
            uint32_t af[4][4], bfr[4][2];
            #pragma unroll
            for (int mt = 0; mt < 4; mt++) {
                const __nv_bfloat16* p = As + (wr + mt * 16 + lr) * ASTRIDE + ks + lc * 2;
                af[mt][0] = *(const uint32_t*)p;
                af[mt][1] = *(const uint32_t*)(p + 8 * ASTRIDE);
                af[mt][2] = *(const uint32_t*)(p + 8);
                af[mt][3] = *(const uint32_t*)(p + 8 * ASTRIDE + 8);
            }
            #pragma unroll
            for (int nt = 0; nt < 4; nt++) {
                const __nv_bfloat16* p = Bs + (wc + nt * 8 + lr) * ASTRIDE + ks + lc * 2;
                bfr[nt][0] = *(const uint32_t*)p;
                bfr[nt][1] = *(const uint32_t*)(p + 8);
            }
            #pragma unroll
            for (int mt = 0; mt < 4; mt++)
                #pragma unroll
                for (int nt = 0; nt < 4; nt++)
                    mma16816(acc[mt][nt], af[mt], bfr[nt]);
        }
        // next iteration's top __syncthreads() protects this stage before reuse
    }

    // ---- store ----
    #pragma unroll
    for (int mt = 0; mt < 4; mt++) {
        const int gr = bm + wr + mt * 16 + lr;
        #pragma unroll
        for (int nt = 0; nt < 4; nt++) {
            const int gc = bn + wc + nt * 8 + lc * 2;
            *(float2*)(C + (size_t)gr * N + gc) =
                make_float2(acc[mt][nt][0], acc[mt][nt][1]);
            *(float2*)(C + (size_t)(gr + 8) * N + gc) =
                make_float2(acc[mt][nt][2], acc[mt][nt][3]);
        }
    }
}

// ---------------------------------------------------------------------------
// Kernel 3: fused epilogue: out = gamma_n*t + A_n*b
// ---------------------------------------------------------------------------
__global__ void __launch_bounds__(512)
epilogue_kernel(const float* __restrict__ T, const float* __restrict__ bvec,
                const float* __restrict__ cvec, float* __restrict__ out, int D)
{
    const int n = blockIdx.x;
    const float* trow = T + (size_t)n * D;
    const int k = threadIdx.x * 4;

    float4 tv = *(const float4*)(trow + k);
    float4 bv = *(const float4*)(bvec + k);

    float st2 = tv.x * tv.x + tv.y * tv.y + tv.z * tv.z + tv.w * tv.w;
    float stb = tv.x * bv.x + tv.y * bv.y + tv.z * bv.z + tv.w * bv.w;
    float sb2 = bv.x * bv.x + bv.y * bv.y + bv.z * bv.z + bv.w * bv.w;

    #pragma unroll
    for (int o = 16; o > 0; o >>= 1) {
        st2 += __shfl_xor_sync(0xffffffffu, st2, o);
        stb += __shfl_xor_sync(0xffffffffu, stb, o);
        sb2 += __shfl_xor_sync(0xffffffffu, sb2, o);
    }
    __shared__ float sh[16][3];
    __shared__ float tot[3];
    const int warp = threadIdx.x >> 5, lane = threadIdx.x & 31;
    if (lane == 0) { sh[warp][0] = st2; sh[warp][1] = stb; sh[warp][2] = sb2; }
    __syncthreads();
    if (warp == 0) {
        float a  = (lane < 16) ? sh[lane][0] : 0.f;
        float b2 = (lane < 16) ? sh[lane][1] : 0.f;
        float c2 = (lane < 16) ? sh[lane][2] : 0.f;
        #pragma unroll
        for (int o = 8; o > 0; o >>= 1) {
            a  += __shfl_xor_sync(0xffffffffu, a,  o);
            b2 += __shfl_xor_sync(0xffffffffu, b2, o);
            c2 += __shfl_xor_sync(0xffffffffu, c2, o);
        }
        if (lane == 0) { tot[0] = a; tot[1] = b2; tot[2] = c2; }
    }
    __syncthreads();

    const float St2 = tot[0], Stb = tot[1], Sb2 = tot[2];
    const float cn  = cvec[n];

    const float r      = cn * sqrtf(St2);
    const float scale1 = fminf(20.0f / fmaxf(r, EPSF), 1.0f);
    const float rp     = scale1 * r;
    const float coef0  = sinhf(rp) / fmaxf(rp, EPSF);
    const float m      = coef0 * scale1 * cn;
    const float ry2    = m * m * St2;
    const float dot    = m * Stb;

    const float b_y   = 1.0f / fmaxf(sqrtf(1.0f + ry2), TINYF);
    const float coefp = b_y / (1.0f + b_y);
    const float p     = coefp * dot;

    const float v_norm2 = Sb2 + 2.0f * p * dot + p * p * ry2;
    const float dxv     = dot + p * ry2;
    const float g_pvv   = fmaxf(v_norm2 - dxv * dxv / (1.0f + ry2), TINYF);
    const float r_g     = sqrtf(g_pvv);

    const float coef2    = -(b_y * b_y * b_y) / ((1.0f + b_y) * (1.0f + b_y));
    const float lambda_x = (1.0f + b_y) / fmaxf(b_y, TINYF);
    const float z        = fminf(r_g, 20.0f);
    float sc;
    if (fabsf(z) < EPSF) sc = 1.0f + z * z / 6.0f;
    else                 sc = sinhf(z) / fmaxf(z, EPSF);
    const float L = lambda_x * sc;

    const float A  = L * coefp;
    const float Bw = A * p + L * coef2 * dxv;

    const float w2 = A * A * Sb2 + 2.0f * A * Bw * dot + Bw * Bw * ry2;
    const float xw = A * dot + Bw * ry2;
    const float b_w = 1.0f / fmaxf(sqrtf(1.0f + w2), TINYF);
    const float coef_g = coefp * xw + (1.0f - b_w) / b_w;

    const float gamma = (1.0f + coef_g + Bw) * m;

    float4 ov;
    ov.x = gamma * tv.x + A * bv.x;
    ov.y = gamma * tv.y + A * bv.y;
    ov.z = gamma * tv.z + A * bv.z;
    ov.w = gamma * tv.w + A * bv.w;
    *(float4*)(out + (size_t)n * D + k) = ov;
}

// ---------------------------------------------------------------------------
extern "C" void kernel_launch(void* const* d_in, const int* in_sizes, int n_in,
                              void* d_out, int out_size)
{
    const float* x = (const float*)d_in[0];   // [M, K]
    const float* W = (const float*)d_in[1];   // [D, K]
    const float* b = (const float*)d_in[2];   // [D]
    float* out = (float*)d_out;

    const int D = in_sizes[2];
    const int K = in_sizes[1] / D;
    const int M = in_sizes[0] / K;

    void *pt, *pc, *pah, *pal, *pbh, *pbl;
    cudaGetSymbolAddress(&pt, g_t);
    cudaGetSymbolAddress(&pc, g_c);
    cudaGetSymbolAddress(&pah, g_Ahi);
    cudaGetSymbolAddress(&pal, g_Alo);
    cudaGetSymbolAddress(&pbh, g_Bhi);
    cudaGetSymbolAddress(&pbl, g_Blo);
    float* T = (float*)pt;
    float* cvec = (float*)pc;
    __nv_bfloat16* Ahi = (__nv_bfloat16*)pah;
    __nv_bfloat16* Alo = (__nv_bfloat16*)pal;
    __nv_bfloat16* Bhi = (__nv_bfloat16*)pbh;
    __nv_bfloat16* Blo = (__nv_bfloat16*)pbl;

    cudaFuncSetAttribute(gemm_mma_kernel,
                         cudaFuncAttributeMaxDynamicSharedMemorySize, SMEM_BYTES);

    convert_split_kernel<<<M, 256>>>(x, Ahi, Alo, cvec, K, 1);
    convert_split_kernel<<<D, 256>>>(W, Bhi, Blo, nullptr, K, 0);

    dim3 grid(D / BN, M / BM);
    gemm_mma_kernel<<<grid, 256, SMEM_BYTES>>>(Ahi, Alo, Bhi, Blo, T, M, D, K);

    epilogue_kernel<<<M, 512>>>(T, b, cvec, out, D);
}

// round 7
// speedup vs baseline: 2.8940x; 2.2870x over previous
#include <cuda_runtime.h>
#include <cuda_bf16.h>
#include <math.h>
#include <stdint.h>

#define EPSF  1e-6f
#define TINYF 1e-15f

#define MAX_M 16384
#define MAX_K 2048
#define MAX_D 2048

// ---------------- scratch (static device allocations only) ----------------
__device__ float g_t[(size_t)MAX_M * MAX_D];          // GEMM result (fp32)
__device__ float g_c[MAX_M];                          // log0 row coefs
__device__ __nv_bfloat16 g_Ahi[(size_t)MAX_M * MAX_K];
__device__ __nv_bfloat16 g_Alo[(size_t)MAX_M * MAX_K];
__device__ __nv_bfloat16 g_Bhi[(size_t)MAX_D * MAX_K];
__device__ __nv_bfloat16 g_Blo[(size_t)MAX_D * MAX_K];

// ---------------- helpers ----------------
__device__ __forceinline__ uint32_t smem_u32(const void* p) {
    uint32_t a;
    asm("{ .reg .u64 t; cvta.to.shared.u64 t, %1; cvt.u32.u64 %0, t; }" : "=r"(a) : "l"(p));
    return a;
}
#define CP16(dst, src) \
    asm volatile("cp.async.cg.shared.global [%0], [%1], 16;" :: "r"(dst), "l"(src) : "memory")
#define CP_COMMIT() asm volatile("cp.async.commit_group;" ::: "memory")
#define CP_WAIT(n)  asm volatile("cp.async.wait_group %0;" :: "n"(n) : "memory")

#define LDSM_X4(r, addr) \
    asm volatile("ldmatrix.sync.aligned.m8n8.x4.shared.b16 {%0,%1,%2,%3}, [%4];" \
        : "=r"((r)[0]), "=r"((r)[1]), "=r"((r)[2]), "=r"((r)[3]) : "r"(addr))

__device__ __forceinline__ void mma16816(float* c, const uint32_t* a,
                                         uint32_t b0, uint32_t b1) {
    asm volatile(
        "mma.sync.aligned.m16n8k16.row.col.f32.bf16.bf16.f32 "
        "{%0,%1,%2,%3}, {%4,%5,%6,%7}, {%8,%9}, {%0,%1,%2,%3};"
        : "+f"(c[0]), "+f"(c[1]), "+f"(c[2]), "+f"(c[3])
        : "r"(a[0]), "r"(a[1]), "r"(a[2]), "r"(a[3]), "r"(b0), "r"(b1));
}

// ---------------------------------------------------------------------------
// Kernel 1: split fp32 row -> (hi, lo) bf16; optionally also log0 coef c[n]
// ---------------------------------------------------------------------------
__global__ void __launch_bounds__(256)
convert_split_kernel(const float* __restrict__ src, __nv_bfloat16* __restrict__ hi,
                     __nv_bfloat16* __restrict__ lo, float* __restrict__ c,
                     int K, int compute_c)
{
    const int n = blockIdx.x;
    const float* row = src + (size_t)n * K;
    __nv_bfloat16* hrow = hi + (size_t)n * K;
    __nv_bfloat16* lrow = lo + (size_t)n * K;

    float s = 0.f;
    for (int k = threadIdx.x * 4; k < K; k += blockDim.x * 4) {
        float4 v = *(const float4*)(row + k);
        s += v.x * v.x + v.y * v.y + v.z * v.z + v.w * v.w;
        __nv_bfloat16 h0 = __float2bfloat16(v.x);
        __nv_bfloat16 h1 = __float2bfloat16(v.y);
        __nv_bfloat16 h2 = __float2bfloat16(v.z);
        __nv_bfloat16 h3 = __float2bfloat16(v.w);
        __nv_bfloat16 l0 = __float2bfloat16(v.x - __bfloat162float(h0));
        __nv_bfloat16 l1 = __float2bfloat16(v.y - __bfloat162float(h1));
        __nv_bfloat16 l2 = __float2bfloat16(v.z - __bfloat162float(h2));
        __nv_bfloat16 l3 = __float2bfloat16(v.w - __bfloat162float(h3));
        ushort4 hu = make_ushort4(*(unsigned short*)&h0, *(unsigned short*)&h1,
                                  *(unsigned short*)&h2, *(unsigned short*)&h3);
        ushort4 lu = make_ushort4(*(unsigned short*)&l0, *(unsigned short*)&l1,
                                  *(unsigned short*)&l2, *(unsigned short*)&l3);
        *(ushort4*)(hrow + k) = hu;
        *(ushort4*)(lrow + k) = lu;
    }
    if (!compute_c) return;

    #pragma unroll
    for (int o = 16; o > 0; o >>= 1) s += __shfl_xor_sync(0xffffffffu, s, o);
    __shared__ float sh[8];
    const int warp = threadIdx.x >> 5, lane = threadIdx.x & 31;
    if (lane == 0) sh[warp] = s;
    __syncthreads();
    if (threadIdx.x == 0) {
        float tot = 0.f;
        #pragma unroll
        for (int w = 0; w < 8; w++) tot += sh[w];
        float nrm = sqrtf(tot);
        c[n] = asinhf(nrm) / fmaxf(nrm, EPSF);
    }
}

// ---------------------------------------------------------------------------
// Kernel 2: t = x @ W^T via split-bf16 3-term sum on mma.sync.m16n8k16.
// BM=BN=128, BK=32, 4-stage cp.async, 128 threads = 4 warps of 64x64 tiles,
// ldmatrix.x4 fragment loads, rows padded to 40 elems (conflict-free LDSM).
// ---------------------------------------------------------------------------
#define BM 128
#define BN 128
#define BK 32
#define STAGES 4
#define ASTRIDE 40                               // elems; 80 B rows
#define A_STAGE_ELEMS (BM * ASTRIDE)             // 5120
#define B_STAGE_ELEMS (BN * ASTRIDE)
#define STAGE_ELEMS (A_STAGE_ELEMS + B_STAGE_ELEMS)
#define STAGE_BYTES (STAGE_ELEMS * 2)            // 20480
#define SMEM_BYTES (STAGES * STAGE_BYTES)        // 81920

__global__ void __launch_bounds__(128, 2)
gemm_mma_kernel(const __nv_bfloat16* __restrict__ Ahi, const __nv_bfloat16* __restrict__ Alo,
                const __nv_bfloat16* __restrict__ Bhi, const __nv_bfloat16* __restrict__ Blo,
                float* __restrict__ C, int M, int N, int K)
{
    extern __shared__ __nv_bfloat16 sm[];

    const int tid  = threadIdx.x;
    const int warp = tid >> 5;
    const int lane = tid & 31;
    const int lr   = lane >> 2;          // 0..7
    const int lc   = lane & 3;           // 0..3
    const int wr   = (warp >> 1) * 64;   // warp row offset
    const int wc   = (warp & 1) * 64;    // warp col offset

    const int bm = blockIdx.y * BM;
    const int bn = blockIdx.x * BN;

    const int KITER = K / BK;            // 64
    const int NIT   = 3 * KITER;         // 192

    // per-lane ldmatrix base offsets (bytes, relative to stage base)
    const int g8 = lane >> 3, r8 = lane & 7;
    const uint32_t aoff = ((wr + (g8 & 1) * 8 + r8) * ASTRIDE + (g8 >> 1) * 8) * 2;
    const uint32_t boff = (uint32_t)A_STAGE_ELEMS * 2 +
                          ((wc + (g8 >> 1) * 8 + r8) * ASTRIDE + (g8 & 1) * 8) * 2;
    const uint32_t sbase = smem_u32(sm);

    float acc[4][8][4];
    #pragma unroll
    for (int i = 0; i < 4; i++)
        #pragma unroll
        for (int j = 0; j < 8; j++)
            #pragma unroll
            for (int q = 0; q < 4; q++) acc[i][j][q] = 0.f;

    // ---- stage loader: 128 threads, A 512 chunks + B 512 chunks of 16B ----
    auto load_stage = [&](int g, int s) {
        const int seg = g / KITER;
        const int kk  = (g - seg * KITER) * BK;
        const __nv_bfloat16* Ag = (seg == 1) ? Alo : Ahi;
        const __nv_bfloat16* Bg = (seg == 2) ? Blo : Bhi;
        const uint32_t As = sbase + s * STAGE_BYTES;
        const uint32_t Bs = As + A_STAGE_ELEMS * 2;
        #pragma unroll
        for (int i = 0; i < 4; i++) {
            const int id  = tid + i * 128;   // 0..511
            const int row = id >> 2;
            const int cg  = id & 3;
            CP16(As + (row * ASTRIDE + cg * 8) * 2,
                 Ag + (size_t)(bm + row) * K + kk + cg * 8);
            CP16(Bs + (row * ASTRIDE + cg * 8) * 2,
                 Bg + (size_t)(bn + row) * K + kk + cg * 8);
        }
    };

    #pragma unroll
    for (int s = 0; s < STAGES - 1; s++) { load_stage(s, s); CP_COMMIT(); }

    for (int g = 0; g < NIT; ++g) {
        CP_WAIT(STAGES - 2);
        __syncthreads();

        const int gn = g + STAGES - 1;
        if (gn < NIT) load_stage(gn, gn % STAGES);
        CP_COMMIT();

        const uint32_t st = sbase + (g % STAGES) * STAGE_BYTES;

        #pragma unroll
        for (int ks = 0; ks < BK; ks += 16) {
            uint32_t af[4][4], bf[4][4];
            #pragma unroll
            for (int mt = 0; mt < 4; mt++)
                LDSM_X4(af[mt], st + aoff + (mt * 16 * ASTRIDE + ks) * 2);
            #pragma unroll
            for (int j = 0; j < 4; j++)
                LDSM_X4(bf[j], st + boff + (j * 16 * ASTRIDE + ks) * 2);
            #pragma unroll
            for (int mt = 0; mt < 4; mt++)
                #pragma unroll
                for (int j = 0; j < 4; j++) {
                    mma16816(acc[mt][2 * j + 0], af[mt], bf[j][0], bf[j][1]);
                    mma16816(acc[mt][2 * j + 1], af[mt], bf[j][2], bf[j][3]);
                }
        }
    }

    // ---- store ----
    #pragma unroll
    for (int mt = 0; mt < 4; mt++) {
        const int gr = bm + wr + mt * 16 + lr;
        #pragma unroll
        for (int nt = 0; nt < 8; nt++) {
            const int gc = bn + wc + nt * 8 + lc * 2;
            *(float2*)(C + (size_t)gr * N + gc) =
                make_float2(acc[mt][nt][0], acc[mt][nt][1]);
            *(float2*)(C + (size_t)(gr + 8) * N + gc) =
                make_float2(acc[mt][nt][2], acc[mt][nt][3]);
        }
    }
}

// ---------------------------------------------------------------------------
// Kernel 3: fused epilogue, one WARP per row (no block barriers).
// Two passes: (1) row sums St2, Stb, Sb2; (2) out = gamma*t + A*b.
// ---------------------------------------------------------------------------
__global__ void __launch_bounds__(256)
epilogue_kernel(const float* __restrict__ T, const float* __restrict__ bvec,
                const float* __restrict__ cvec, float* __restrict__ out, int D)
{
    const int warp = threadIdx.x >> 5;
    const int lane = threadIdx.x & 31;
    const int n = blockIdx.x * 8 + warp;
    const float* trow = T + (size_t)n * D;

    float st2 = 0.f, stb = 0.f, sb2 = 0.f;
    #pragma unroll
    for (int i = 0; i < 16; i++) {           // D=2048: 16 x 32 lanes x 4
        const int k = (lane + i * 32) * 4;
        float4 tv = *(const float4*)(trow + k);
        float4 bv = *(const float4*)(bvec + k);
        st2 += tv.x * tv.x + tv.y * tv.y + tv.z * tv.z + tv.w * tv.w;
        stb += tv.x * bv.x + tv.y * bv.y + tv.z * bv.z + tv.w * bv.w;
        sb2 += bv.x * bv.x + bv.y * bv.y + bv.z * bv.z + bv.w * bv.w;
    }
    #pragma unroll
    for (int o = 16; o > 0; o >>= 1) {
        st2 += __shfl_xor_sync(0xffffffffu, st2, o);
        stb += __shfl_xor_sync(0xffffffffu, stb, o);
        sb2 += __shfl_xor_sync(0xffffffffu, sb2, o);
    }

    const float St2 = st2, Stb = stb, Sb2 = sb2;
    const float cn  = cvec[n];

    // scalar chain (all lanes redundantly; matches reference fp32 math)
    const float r      = cn * sqrtf(St2);
    const float scale1 = fminf(20.0f / fmaxf(r, EPSF), 1.0f);
    const float rp     = scale1 * r;
    const float coef0  = sinhf(rp) / fmaxf(rp, EPSF);
    const float m      = coef0 * scale1 * cn;
    const float ry2    = m * m * St2;
    const float dot    = m * Stb;

    const float b_y   = 1.0f / fmaxf(sqrtf(1.0f + ry2), TINYF);
    const float coefp = b_y / (1.0f + b_y);
    const float p     = coefp * dot;

    const float v_norm2 = Sb2 + 2.0f * p * dot + p * p * ry2;
    const float dxv     = dot + p * ry2;
    const float g_pvv   = fmaxf(v_norm2 - dxv * dxv / (1.0f + ry2), TINYF);
    const float r_g     = sqrtf(g_pvv);

    const float coef2    = -(b_y * b_y * b_y) / ((1.0f + b_y) * (1.0f + b_y));
    const float lambda_x = (1.0f + b_y) / fmaxf(b_y, TINYF);
    const float z        = fminf(r_g, 20.0f);
    float sc;
    if (fabsf(z) < EPSF) sc = 1.0f + z * z / 6.0f;
    else                 sc = sinhf(z) / fmaxf(z, EPSF);
    const float L = lambda_x * sc;

    const float A  = L * coefp;
    const float Bw = A * p + L * coef2 * dxv;

    const float w2 = A * A * Sb2 + 2.0f * A * Bw * dot + Bw * Bw * ry2;
    const float xw = A * dot + Bw * ry2;
    const float b_w = 1.0f / fmaxf(sqrtf(1.0f + w2), TINYF);
    const float coef_g = coefp * xw + (1.0f - b_w) / b_w;

    const float gamma = (1.0f + coef_g + Bw) * m;

    float* orow = out + (size_t)n * D;
    #pragma unroll
    for (int i = 0; i < 16; i++) {
        const int k = (lane + i * 32) * 4;
        float4 tv = *(const float4*)(trow + k);    // L1/L2 hit from pass 1
        float4 bv = *(const float4*)(bvec + k);
        float4 ov;
        ov.x = gamma * tv.x + A * bv.x;
        ov.y = gamma * tv.y + A * bv.y;
        ov.z = gamma * tv.z + A * bv.z;
        ov.w = gamma * tv.w + A * bv.w;
        *(float4*)(orow + k) = ov;
    }
}

// ---------------------------------------------------------------------------
extern "C" void kernel_launch(void* const* d_in, const int* in_sizes, int n_in,
                              void* d_out, int out_size)
{
    const float* x = (const float*)d_in[0];   // [M, K]
    const float* W = (const float*)d_in[1];   // [D, K]
    const float* b = (const float*)d_in[2];   // [D]
    float* out = (float*)d_out;

    const int D = in_sizes[2];
    const int K = in_sizes[1] / D;
    const int M = in_sizes[0] / K;

    void *pt, *pc, *pah, *pal, *pbh, *pbl;
    cudaGetSymbolAddress(&pt, g_t);
    cudaGetSymbolAddress(&pc, g_c);
    cudaGetSymbolAddress(&pah, g_Ahi);
    cudaGetSymbolAddress(&pal, g_Alo);
    cudaGetSymbolAddress(&pbh, g_Bhi);
    cudaGetSymbolAddress(&pbl, g_Blo);
    float* T = (float*)pt;
    float* cvec = (float*)pc;
    __nv_bfloat16* Ahi = (__nv_bfloat16*)pah;
    __nv_bfloat16* Alo = (__nv_bfloat16*)pal;
    __nv_bfloat16* Bhi = (__nv_bfloat16*)pbh;
    __nv_bfloat16* Blo = (__nv_bfloat16*)pbl;

    cudaFuncSetAttribute(gemm_mma_kernel,
                         cudaFuncAttributeMaxDynamicSharedMemorySize, SMEM_BYTES);

    convert_split_kernel<<<M, 256>>>(x, Ahi, Alo, cvec, K, 1);
    convert_split_kernel<<<D, 256>>>(W, Bhi, Blo, nullptr, K, 0);

    dim3 grid(D / BN, M / BM);
    gemm_mma_kernel<<<grid, 128, SMEM_BYTES>>>(Ahi, Alo, Bhi, Blo, T, M, D, K);

    epilogue_kernel<<<M / 8, 256>>>(T, b, cvec, out, D);
}